// round 15
// baseline (speedup 1.0000x reference)
#include <cuda_runtime.h>
#include <cuda_fp16.h>
#include <cstdint>
#include <math.h>

#define L 256
#define C 1024
#define NEC 2000
#define NPAIR 65536

// ---------------- scratch (__device__ globals; no allocations) ----------------
__device__ float g_mask[L];
__device__ int   g_idx[257];                       // compacted unmasked indices
__device__ int   g_U;                              // count of unmasked positions
__device__ float g_z[C * L];                       // z[c][l], masked, transposed
__device__ float g_tmp[C];                         // lin1 output
__device__ float g_h[(size_t)C * NPAIR];           // h[o][i][j]  (sparse: real pairs only)
__device__ float g_row[(size_t)C * 257];           // pseudo-pair values: [o][real j], [o][256]=const
__device__ float g_part[16 * NPAIR];               // conv2 channel-group partials
__device__ __half g_wh[(size_t)C * 2048];          // W in fp16, chunk-interleaved

// ---------------- helpers ----------------
__device__ __forceinline__ uint32_t smem_to_u32(const void* p) {
    uint32_t a;
    asm("{ .reg .u64 t; cvta.to.shared.u64 t, %1; cvt.u32.u64 %0, t; }" : "=r"(a) : "l"(p));
    return a;
}
#define CVT_F16X2(res, a, b) \
    asm("cvt.rn.f16x2.f32 %0, %1, %2;" : "=r"(res) : "f"(b), "f"(a))
#define SWZ128(x) ((x) ^ (((x) >> 3) & 0x70))

__device__ __forceinline__ void ldsm_x4(uint32_t addr, uint32_t* r) {
    asm volatile("ldmatrix.sync.aligned.m8n8.x4.shared.b16 {%0,%1,%2,%3}, [%4];"
                 : "=r"(r[0]), "=r"(r[1]), "=r"(r[2]), "=r"(r[3]) : "r"(addr));
}
__device__ __forceinline__ void mma16816(float* c, const uint32_t* a, uint32_t b0, uint32_t b1) {
    asm volatile(
        "mma.sync.aligned.m16n8k16.row.col.f32.f16.f16.f32 "
        "{%0,%1,%2,%3}, {%4,%5,%6,%7}, {%8,%9}, {%0,%1,%2,%3};"
        : "+f"(c[0]), "+f"(c[1]), "+f"(c[2]), "+f"(c[3])
        : "r"(a[0]), "r"(a[1]), "r"(a[2]), "r"(a[3]), "r"(b0), "r"(b1));
}

// SMEM layout (byte offsets from 1024-aligned base), double-buffered
#define SM_A(s)  ((s) * 49152)
#define SM_B(s)  ((s) * 49152 + 16384)
#define SM_ZC(s) (98304 + (s) * 4352)
#define SM_SIX 107008
#define SMEM_BYTES (107008 + 128 + 1024)

// ---------------- prep: mask + compacted index list ----------------
__global__ void k_mask(const int* __restrict__ am) {
    __shared__ int red[256];
    __shared__ int scn[256];
    int l = threadIdx.x;
    int v = am[l];
    red[l] = v;
    __syncthreads();
    for (int off = 128; off; off >>= 1) {
        if (l < off) red[l] += red[l + off];
        __syncthreads();
    }
    int s = red[0];
    float m = (float)v;
    if (l == 0 || l == s) m = 0.f;
    g_mask[l] = m;
    int flag = (m != 0.f) ? 1 : 0;
    scn[l] = flag;
    __syncthreads();
    for (int off = 1; off < 256; off <<= 1) {
        int t = (l >= off) ? scn[l - off] : 0;
        __syncthreads();
        scn[l] += t;
        __syncthreads();
    }
    if (flag) g_idx[scn[l] - 1] = l;
    if (l == 255) g_U = scn[255];
}

__global__ void k_z(const float* __restrict__ attn) {
    int l = blockIdx.x;
    float m = g_mask[l];
    for (int c = threadIdx.x; c < C; c += blockDim.x)
        g_z[c * L + l] = attn[l * C + c] * m;
}

// ---------------- W -> fp16, chunk-interleaved, float4 vectorized ----------------
__global__ void k_wsplit(const float* __restrict__ W) {
    int idx = (blockIdx.x * 256 + threadIdx.x) * 4;
    int o = idx >> 11;
    int k = idx & 2047;
    int kc = k >> 6, kk = k & 63;
    int c = (kk < 32) ? (kc * 32 + kk) : (1024 + kc * 32 + kk - 32);
    float4 v = *(const float4*)(W + (size_t)o * 2048 + c);
    __half2* dh = (__half2*)(g_wh + idx);
    dh[0] = __floats2half2_rn(v.x, v.y);
    dh[1] = __floats2half2_rn(v.z, v.w);
}

// ---------------- logits head ----------------
__global__ void k_lin1(const float* __restrict__ pooled, const float* __restrict__ w,
                       const float* __restrict__ b) {
    int gw = (blockIdx.x * blockDim.x + threadIdx.x) >> 5;
    int lane = threadIdx.x & 31;
    if (gw >= C) return;
    const float* row = w + (size_t)gw * C;
    float s = 0.f;
    for (int c2 = lane; c2 < C; c2 += 32) s += row[c2] * pooled[c2];
#pragma unroll
    for (int off = 16; off; off >>= 1) s += __shfl_xor_sync(0xffffffffu, s, off);
    if (lane == 0) g_tmp[gw] = s + b[gw];
}

__global__ void k_cls(const float* __restrict__ w, const float* __restrict__ b,
                      float* __restrict__ out) {
    int gw = (blockIdx.x * blockDim.x + threadIdx.x) >> 5;
    int lane = threadIdx.x & 31;
    if (gw >= NEC) return;
    const float* row = w + (size_t)gw * C;
    float s = 0.f;
    for (int c2 = lane; c2 < C; c2 += 32) s += row[c2] * g_tmp[c2];
#pragma unroll
    for (int off = 16; off; off >>= 1) s += __shfl_xor_sync(0xffffffffu, s, off);
    if (lane == 0) out[gw] = s + b[gw];
}

// ---------------- main GEMM: compacted pairs, single-pass FP16, 16 warps ----------------
// CTA: 128 outputs x 256 pairs. 16 warps = 4(M) x 4(N), warp tile 32x64.
__global__ void __launch_bounds__(512, 1) k_hmma(const float* __restrict__ b1) {
    int ib = blockIdx.y, jb = blockIdx.z;
    int U = g_U;
    int T = (U + 16) >> 4;
    if (jb < ib || ib >= T || jb >= T) return;
    int m0 = blockIdx.x * 128;
    int i0 = ib * 16, j0 = jb * 16;

    extern __shared__ char smem_raw[];
    char* sm = (char*)(((uintptr_t)smem_raw + 1023) & ~(uintptr_t)1023);
    uint32_t sb = smem_to_u32(sm);
    int* six = (int*)(sm + SM_SIX);

    int tid = threadIdx.x, wid = tid >> 5, lane = tid & 31;
    int wm = wid >> 2, wn = wid & 3;         // 4x4 warps; warp tile 32(M) x 64(N)
    int arow = lane & 15, aseg = lane >> 4;
    int brow = (lane & 7) + ((lane >> 4) << 3);
    int bhalf = (lane >> 3) & 1;

    if (tid < 32) {
        int a = (tid < 16) ? (i0 + tid) : (j0 + tid - 16);
        six[tid] = (a < U) ? g_idx[a] : -1;
    }
    __syncthreads();

    float acc[2][8][4];
#pragma unroll
    for (int a = 0; a < 2; a++)
#pragma unroll
        for (int b = 0; b < 8; b++)
#pragma unroll
            for (int r = 0; r < 4; r++) acc[a][b][r] = 0.f;

    float pz[2];
    float4 pw[2];

    auto ldgc = [&](int kc) {
        int c0 = kc * 32;
#pragma unroll
        for (int r = 0; r < 2; r++) {
            int id2 = tid + r * 512;
            int ch = id2 >> 5, l2 = id2 & 31;
            int pos = six[l2];
            pz[r] = (pos >= 0) ? g_z[(c0 + ch) * L + pos] : 0.f;
        }
#pragma unroll
        for (int r = 0; r < 2; r++) {
            int q = tid + r * 512;
            int row = q >> 3, seg = q & 7;
            pw[r] = *(const float4*)((const char*)(g_wh + (size_t)(m0 + row) * 2048 + kc * 64) + seg * 16);
        }
    };
    auto storec = [&](int st) {
        float* zcs = (float*)(sm + SM_ZC(st));
#pragma unroll
        for (int r = 0; r < 2; r++) {
            int id2 = tid + r * 512;
            int ch = id2 >> 5, l2 = id2 & 31;
            zcs[ch * 33 + l2] = pz[r];
        }
#pragma unroll
        for (int r = 0; r < 2; r++) {
            int q = tid + r * 512;
            int row = q >> 3, seg = q & 7;
            uint32_t swo = SWZ128((uint32_t)(row * 128 + seg * 16));
            *(float4*)(sm + SM_A(st) + swo) = pw[r];
        }
    };
    int prow = tid & 255;                     // feat row for gen
    int ii = prow >> 4, jj = prow & 15;
    int gbase = (tid >> 8) * 2;               // threads 0-255: groups 0-1; 256-511: groups 2-3
    auto genf = [&](int st) {
        const float* zi = (const float*)(sm + SM_ZC(st)) + ii;
        const float* zj = (const float*)(sm + SM_ZC(st)) + 16 + jj;
#pragma unroll
        for (int gq = 0; gq < 2; gq++) {
            int g = gbase + gq;
            uint32_t dh[4], mh[4];
#pragma unroll
            for (int u = 0; u < 4; u++) {
                int ch = g * 8 + u * 2;
                float a0 = zi[ch * 33], a1 = zi[(ch + 1) * 33];
                float b0 = zj[ch * 33], b1v = zj[(ch + 1) * 33];
                float d0 = fabsf(a0 - b0), d1 = fabsf(a1 - b1v);
                float p0 = a0 * b0, p1 = a1 * b1v;
                uint32_t rh; CVT_F16X2(rh, d0, d1);
                uint32_t qh; CVT_F16X2(qh, p0, p1);
                dh[u] = rh; mh[u] = qh;
            }
            uint32_t bod = SWZ128((uint32_t)(prow * 128 + g * 16));
            uint32_t bom = SWZ128((uint32_t)(prow * 128 + 64 + g * 16));
            *(uint4*)(sm + SM_B(st) + bod) = make_uint4(dh[0], dh[1], dh[2], dh[3]);
            *(uint4*)(sm + SM_B(st) + bom) = make_uint4(mh[0], mh[1], mh[2], mh[3]);
        }
    };
    auto mmastep = [&](int st, int ks) {
        int kb = ks * 32;
        uint32_t af[2][4], bb[4][4];
#pragma unroll
        for (int am = 0; am < 2; am++) {
            uint32_t off = SWZ128((uint32_t)((wm * 32 + am * 16 + arow) * 128 + kb + aseg * 16));
            ldsm_x4(sb + SM_A(st) + off, af[am]);
        }
#pragma unroll
        for (int bq = 0; bq < 4; bq++) {
            uint32_t off = SWZ128((uint32_t)((wn * 64 + bq * 16 + brow) * 128 + kb + bhalf * 16));
            ldsm_x4(sb + SM_B(st) + off, bb[bq]);
        }
#pragma unroll
        for (int am = 0; am < 2; am++)
#pragma unroll
            for (int bq = 0; bq < 4; bq++) {
                mma16816(acc[am][2 * bq], af[am], bb[bq][0], bb[bq][1]);
                mma16816(acc[am][2 * bq + 1], af[am], bb[bq][2], bb[bq][3]);
            }
    };

    ldgc(0);
    storec(0);
    __syncthreads();
    genf(0);

    for (int kc = 0; kc < 32; kc++) {
        int s = kc & 1, ns = s ^ 1;
        bool have = (kc < 31);
        if (have) ldgc(kc + 1);
        __syncthreads();
        if (have) storec(ns);
        mmastep(s, 0);
        mmastep(s, 1);
        if (have) {
            __syncthreads();
            genf(ns);
        }
        mmastep(s, 2);
        mmastep(s, 3);
    }

    int qrow = lane >> 2, qcol = (lane & 3) * 2;
#pragma unroll
    for (int am = 0; am < 2; am++) {
        int mb = wm * 32 + am * 16;
        float bias0 = b1[m0 + mb + qrow];
        float bias1 = b1[m0 + mb + qrow + 8];
#pragma unroll
        for (int bn = 0; bn < 8; bn++) {
            int n = wn * 64 + bn * 8 + qcol;
#pragma unroll
            for (int r = 0; r < 4; r++) {
                int mrow = mb + qrow + (r >> 1) * 8;
                int nn = n + (r & 1);
                float v = acc[am][bn][r] + ((r >> 1) ? bias1 : bias0);
                v = fmaxf(v, 0.f);
                int sa = nn >> 4, sj = nn & 15;
                int ri = six[sa], rj = six[16 + sj];
                int o = m0 + mrow;
                if (ri >= 0 && rj >= 0) {
                    float* hp = g_h + ((size_t)o << 16);
                    hp[ri * 256 + rj] = v;
                    hp[rj * 256 + ri] = v;
                } else {
                    int pa = i0 + sa, pb = j0 + sj;
                    if (pa == U && rj >= 0)      g_row[(size_t)o * 257 + rj] = v;
                    else if (pb == U && ri >= 0) g_row[(size_t)o * 257 + ri] = v;
                    else if (pa == U && pb == U) g_row[(size_t)o * 257 + 256] = v;
                }
            }
        }
    }
}

// ---------------- 7x7 conv: masked-row factorization + double-buffered prefetch ----------------
__global__ __launch_bounds__(256) void k_conv2(const float* __restrict__ w2) {
    int jb = blockIdx.x, ib = blockIdx.y;
    if (jb < ib) return;
    int g = blockIdx.z;
    __shared__ float sT[2][38][40];
    __shared__ float su[2][40];
    __shared__ float sKc[2][49];
    __shared__ float sS[2][7][32];
    __shared__ int sMi[38], sMj[38];
    int tid = threadIdx.x;
    int tx = tid & 31, ty = tid >> 5;
    int i0 = ib * 32, j0 = jb * 32;
    int rbase = ty * 4;
    float acc[4] = {0.f, 0.f, 0.f, 0.f};

    if (tid < 38) {
        int gi = i0 - 3 + tid;
        sMi[tid] = ((unsigned)gi < 256u) ? ((g_mask[gi] == 0.f) ? 1 : 0) : 2;
        int gj = j0 - 3 + tid;
        sMj[tid] = ((unsigned)gj < 256u) ? ((g_mask[gj] == 0.f) ? 1 : 0) : 2;
    }
    __syncthreads();

    float rT[6], rU, rK;
    auto ldg_stage = [&](int c) {
        const float* hp = g_h + ((size_t)c << 16);
        const float* rw = g_row + (size_t)c * 257;
#pragma unroll
        for (int q = 0; q < 6; q++) {
            rT[q] = 0.f;
            int t = tid + q * 256;
            if (t < 38 * 38) {
                int r = t / 38, cc = t - r * 38;
                if (sMi[r] == 0) {
                    int gi = i0 - 3 + r, gj = j0 - 3 + cc;
                    int mj = sMj[cc];
                    if (mj == 0)      rT[q] = hp[gi * 256 + gj];
                    else if (mj == 1) rT[q] = rw[gi];
                }
            }
        }
        rU = 0.f;
        if (tid < 38) {
            int mj = sMj[tid];
            if (mj == 0)      rU = rw[j0 - 3 + tid];
            else if (mj == 1) rU = rw[256];
        }
        rK = (tid < 49) ? w2[c * 49 + tid] : 0.f;
    };
    auto sts_stage = [&](int s) {
#pragma unroll
        for (int q = 0; q < 6; q++) {
            int t = tid + q * 256;
            if (t < 38 * 38) {
                int r = t / 38, cc = t - r * 38;
                sT[s][r][cc] = rT[q];
            }
        }
        if (tid < 38) su[s][tid] = rU;
        if (tid < 49) sKc[s][tid] = rK;
    };
    auto computeS = [&](int s) {
        if (tid < 224) {
            int a = tid >> 5, j = tid & 31;
            float v = 0.f;
#pragma unroll
            for (int b = 0; b < 7; b++) v += sKc[s][a * 7 + b] * su[s][j + b];
            sS[s][a][j] = v;
        }
    };

    ldg_stage(g * 64);
    sts_stage(0);
    __syncthreads();
    computeS(0);

    for (int ci = 0; ci < 64; ci++) {
        int c = g * 64 + ci;
        int s = ci & 1, ns = s ^ 1;
        bool have = (ci < 63);
        if (have) ldg_stage(c + 1);
        __syncthreads();
        if (have) sts_stage(ns);

        float wk[49];
#pragma unroll
        for (int q = 0; q < 49; q++) wk[q] = sKc[s][q];
#pragma unroll
        for (int rr = 0; rr < 10; rr++) {
            int cls = sMi[rbase + rr];
            if (cls == 0) {
                float seg[7];
#pragma unroll
                for (int b = 0; b < 7; b++) seg[b] = sT[s][rbase + rr][tx + b];
#pragma unroll
                for (int r = 0; r < 4; r++) {
                    int a = rr - r;
                    if (a >= 0 && a < 7) {
#pragma unroll
                        for (int b = 0; b < 7; b++)
                            acc[r] += wk[a * 7 + b] * seg[b];
                    }
                }
            } else if (cls == 1) {
#pragma unroll
                for (int r = 0; r < 4; r++) {
                    int a = rr - r;
                    if (a >= 0 && a < 7) acc[r] += sS[s][a][tx];
                }
            }
        }

        if (have) {
            __syncthreads();
            computeS(ns);
        }
    }

#pragma unroll
    for (int r = 0; r < 4; r++) {
        int i = i0 + rbase + r, j = j0 + tx;
        g_part[g * NPAIR + i * 256 + j] = acc[r];
    }
}

__global__ void k_red(const float* __restrict__ b2, float* __restrict__ out) {
    int idx = blockIdx.x * 256 + threadIdx.x;
    int i = idx >> 8, j = idx & 255;
    if (j < i) return;
    float s = b2[0];
#pragma unroll
    for (int g = 0; g < 16; g++) s += g_part[g * NPAIR + idx];
    float v = 1.f / (1.f + expf(-s));
    out[NEC + i * 256 + j] = v;
    out[NEC + j * 256 + i] = v;
}

extern "C" void kernel_launch(void* const* d_in, const int* in_sizes, int n_in,
                              void* d_out, int out_size) {
    const float* attn    = (const float*)d_in[0];
    const float* pooled  = (const float*)d_in[1];
    const int*   am      = (const int*)d_in[2];
    const float* lin1_w  = (const float*)d_in[3];
    const float* lin1_b  = (const float*)d_in[4];
    const float* cls_w   = (const float*)d_in[5];
    const float* cls_b   = (const float*)d_in[6];
    const float* conv1_w = (const float*)d_in[7];
    const float* conv1_b = (const float*)d_in[8];
    const float* conv2_w = (const float*)d_in[9];
    const float* conv2_b = (const float*)d_in[10];
    float* out = (float*)d_out;

    cudaFuncSetAttribute(k_hmma, cudaFuncAttributeMaxDynamicSharedMemorySize, SMEM_BYTES);

    k_mask<<<1, 256>>>(am);
    k_z<<<256, 256>>>(attn);
    k_wsplit<<<2048, 256>>>(conv1_w);
    k_hmma<<<dim3(8, 17, 17), 512, SMEM_BYTES>>>(conv1_b);
    k_conv2<<<dim3(8, 8, 16), 256>>>(conv2_w);
    k_red<<<256, 256>>>(conv2_b, out);
    k_lin1<<<128, 256>>>(pooled, lin1_w, lin1_b);
    k_cls<<<250, 256>>>(cls_w, cls_b, out);
}

// round 16
// speedup vs baseline: 1.0038x; 1.0038x over previous
#include <cuda_runtime.h>
#include <cuda_fp16.h>
#include <cstdint>
#include <math.h>

#define L 256
#define C 1024
#define NEC 2000
#define NPAIR 65536

// ---------------- scratch (__device__ globals; no allocations) ----------------
__device__ float g_mask[L];
__device__ int   g_idx[257];                       // compacted unmasked indices
__device__ int   g_U;                              // count of unmasked positions
__device__ float g_z[C * L];                       // z[c][l], masked, transposed
__device__ float g_tmp[C];                         // lin1 output
__device__ float g_h[(size_t)C * NPAIR];           // h[o][i][j]  (sparse: real pairs only)
__device__ float g_row[(size_t)C * 257];           // pseudo-pair values
__device__ float g_part[16 * NPAIR];               // conv2 channel-group partials
__device__ __half g_wh[(size_t)C * 2048];          // W in fp16, chunk-interleaved
// feat tiles, fp16, pre-SW128-swizzled SMEM image: [tp = ib*17+jb][kc][32KB]
__device__ __align__(16) char g_feat[(size_t)289 << 20];

// ---------------- helpers ----------------
__device__ __forceinline__ uint32_t smem_to_u32(const void* p) {
    uint32_t a;
    asm("{ .reg .u64 t; cvta.to.shared.u64 t, %1; cvt.u32.u64 %0, t; }" : "=r"(a) : "l"(p));
    return a;
}
#define CVT_F16X2(res, a, b) \
    asm("cvt.rn.f16x2.f32 %0, %1, %2;" : "=r"(res) : "f"(b), "f"(a))
#define SWZ128(x) ((x) ^ (((x) >> 3) & 0x70))
#define CP16(dst, src) \
    asm volatile("cp.async.cg.shared.global [%0], [%1], 16;" :: "r"(dst), "l"(src) : "memory")
#define CP_COMMIT() asm volatile("cp.async.commit_group;" ::: "memory")
#define CP_WAIT1()  asm volatile("cp.async.wait_group 1;" ::: "memory")

__device__ __forceinline__ void ldsm_x4(uint32_t addr, uint32_t* r) {
    asm volatile("ldmatrix.sync.aligned.m8n8.x4.shared.b16 {%0,%1,%2,%3}, [%4];"
                 : "=r"(r[0]), "=r"(r[1]), "=r"(r[2]), "=r"(r[3]) : "r"(addr));
}
__device__ __forceinline__ void mma16816(float* c, const uint32_t* a, uint32_t b0, uint32_t b1) {
    asm volatile(
        "mma.sync.aligned.m16n8k16.row.col.f32.f16.f16.f32 "
        "{%0,%1,%2,%3}, {%4,%5,%6,%7}, {%8,%9}, {%0,%1,%2,%3};"
        : "+f"(c[0]), "+f"(c[1]), "+f"(c[2]), "+f"(c[3])
        : "r"(a[0]), "r"(a[1]), "r"(a[2]), "r"(a[3]), "r"(b0), "r"(b1));
}

// SMEM: 3-stage ring of (A 16KB + B 32KB)
#define SM_A(s) ((s) * 49152)
#define SM_B(s) ((s) * 49152 + 16384)
#define SM_SIX 147456
#define SMEM_BYTES (147456 + 128 + 1024)

// ---------------- prep: mask + compacted index list ----------------
__global__ void k_mask(const int* __restrict__ am) {
    __shared__ int red[256];
    __shared__ int scn[256];
    int l = threadIdx.x;
    int v = am[l];
    red[l] = v;
    __syncthreads();
    for (int off = 128; off; off >>= 1) {
        if (l < off) red[l] += red[l + off];
        __syncthreads();
    }
    int s = red[0];
    float m = (float)v;
    if (l == 0 || l == s) m = 0.f;
    g_mask[l] = m;
    int flag = (m != 0.f) ? 1 : 0;
    scn[l] = flag;
    __syncthreads();
    for (int off = 1; off < 256; off <<= 1) {
        int t = (l >= off) ? scn[l - off] : 0;
        __syncthreads();
        scn[l] += t;
        __syncthreads();
    }
    if (flag) g_idx[scn[l] - 1] = l;
    if (l == 255) g_U = scn[255];
}

__global__ void k_z(const float* __restrict__ attn) {
    int l = blockIdx.x;
    float m = g_mask[l];
    for (int c = threadIdx.x; c < C; c += blockDim.x)
        g_z[c * L + l] = attn[l * C + c] * m;
}

// ---------------- W -> fp16, chunk-interleaved ----------------
__global__ void k_wsplit(const float* __restrict__ W) {
    int idx = (blockIdx.x * 256 + threadIdx.x) * 4;
    int o = idx >> 11;
    int k = idx & 2047;
    int kc = k >> 6, kk = k & 63;
    int c = (kk < 32) ? (kc * 32 + kk) : (1024 + kc * 32 + kk - 32);
    float4 v = *(const float4*)(W + (size_t)o * 2048 + c);
    __half2* dh = (__half2*)(g_wh + idx);
    dh[0] = __floats2half2_rn(v.x, v.y);
    dh[1] = __floats2half2_rn(v.z, v.w);
}

// ---------------- feat generation: once per tile-pair, pre-swizzled fp16 ----------------
// grid (17, 17, 8): (ib, jb, kslice of 4 chunks). block 256.
__global__ __launch_bounds__(256) void k_feat() {
    int ib = blockIdx.x, jb = blockIdx.y;
    int U = g_U;
    int T = (U + 16) >> 4;
    if (jb < ib || ib >= T || jb >= T) return;
    int i0 = ib * 16, j0 = jb * 16;
    int tp = ib * 17 + jb;

    __shared__ float zc[32 * 33];
    __shared__ int six[32];
    int tid = threadIdx.x;
    if (tid < 32) {
        int a = (tid < 16) ? (i0 + tid) : (j0 + tid - 16);
        six[tid] = (a < U) ? g_idx[a] : -1;
    }
    __syncthreads();

    int ii = tid >> 4, jj = tid & 15;
    char* fb0 = g_feat + ((size_t)tp << 20);

    for (int kc = blockIdx.z * 4; kc < blockIdx.z * 4 + 4; kc++) {
        __syncthreads();
        int c0 = kc * 32;
#pragma unroll
        for (int r = 0; r < 4; r++) {
            int id2 = tid + r * 256;
            int ch = id2 >> 5, l2 = id2 & 31;
            int pos = six[l2];
            zc[ch * 33 + l2] = (pos >= 0) ? g_z[(c0 + ch) * L + pos] : 0.f;
        }
        __syncthreads();
        const float* zi = zc + ii;
        const float* zj = zc + 16 + jj;
        char* fb = fb0 + (size_t)kc * 32768;
#pragma unroll
        for (int g = 0; g < 4; g++) {
            uint32_t dh[4], mh[4];
#pragma unroll
            for (int u = 0; u < 4; u++) {
                int ch = g * 8 + u * 2;
                float a0 = zi[ch * 33], a1 = zi[(ch + 1) * 33];
                float b0 = zj[ch * 33], b1v = zj[(ch + 1) * 33];
                float d0 = fabsf(a0 - b0), d1 = fabsf(a1 - b1v);
                float p0 = a0 * b0, p1 = a1 * b1v;
                uint32_t rh; CVT_F16X2(rh, d0, d1);
                uint32_t qh; CVT_F16X2(qh, p0, p1);
                dh[u] = rh; mh[u] = qh;
            }
            *(uint4*)(fb + SWZ128((uint32_t)(tid * 128 + g * 16))) =
                make_uint4(dh[0], dh[1], dh[2], dh[3]);
            *(uint4*)(fb + SWZ128((uint32_t)(tid * 128 + 64 + g * 16))) =
                make_uint4(mh[0], mh[1], mh[2], mh[3]);
        }
    }
}

// ---------------- logits head ----------------
__global__ void k_lin1(const float* __restrict__ pooled, const float* __restrict__ w,
                       const float* __restrict__ b) {
    int gw = (blockIdx.x * blockDim.x + threadIdx.x) >> 5;
    int lane = threadIdx.x & 31;
    if (gw >= C) return;
    const float* row = w + (size_t)gw * C;
    float s = 0.f;
    for (int c2 = lane; c2 < C; c2 += 32) s += row[c2] * pooled[c2];
#pragma unroll
    for (int off = 16; off; off >>= 1) s += __shfl_xor_sync(0xffffffffu, s, off);
    if (lane == 0) g_tmp[gw] = s + b[gw];
}

__global__ void k_cls(const float* __restrict__ w, const float* __restrict__ b,
                      float* __restrict__ out) {
    int gw = (blockIdx.x * blockDim.x + threadIdx.x) >> 5;
    int lane = threadIdx.x & 31;
    if (gw >= NEC) return;
    const float* row = w + (size_t)gw * C;
    float s = 0.f;
    for (int c2 = lane; c2 < C; c2 += 32) s += row[c2] * g_tmp[c2];
#pragma unroll
    for (int off = 16; off; off >>= 1) s += __shfl_xor_sync(0xffffffffu, s, off);
    if (lane == 0) out[gw] = s + b[gw];
}

// ---------------- main GEMM: pure cp.async-staged FP16 HMMA ----------------
// CTA: 128 outputs x 256 pairs, 16 warps = 4(M) x 4(N), warp tile 32x64.
// 3-stage cp.async ring, one barrier per chunk.
__global__ void __launch_bounds__(512, 1) k_hmma(const float* __restrict__ b1) {
    int ib = blockIdx.y, jb = blockIdx.z;
    int U = g_U;
    int T = (U + 16) >> 4;
    if (jb < ib || ib >= T || jb >= T) return;
    int m0 = blockIdx.x * 128;
    int i0 = ib * 16, j0 = jb * 16;
    int tp = ib * 17 + jb;

    extern __shared__ char smem_raw[];
    char* sm = (char*)(((uintptr_t)smem_raw + 1023) & ~(uintptr_t)1023);
    uint32_t sb = smem_to_u32(sm);
    int* six = (int*)(sm + SM_SIX);

    int tid = threadIdx.x, wid = tid >> 5, lane = tid & 31;
    int wm = wid >> 2, wn = wid & 3;
    int arow = lane & 15, aseg = lane >> 4;
    int brow = (lane & 7) + ((lane >> 4) << 3);
    int bhalf = (lane >> 3) & 1;

    if (tid < 32) {
        int a = (tid < 16) ? (i0 + tid) : (j0 + tid - 16);
        six[tid] = (a < U) ? g_idx[a] : -1;
    }

    float acc[2][8][4];
#pragma unroll
    for (int a = 0; a < 2; a++)
#pragma unroll
        for (int b = 0; b < 8; b++)
#pragma unroll
            for (int r = 0; r < 4; r++) acc[a][b][r] = 0.f;

    const char* fb0 = g_feat + ((size_t)tp << 20);

    auto cpin = [&](int kc, int st) {
        // A: W tile (swizzle applied on SMEM destination)
#pragma unroll
        for (int r = 0; r < 2; r++) {
            int q = tid + r * 512;
            int row = q >> 3, seg = q & 7;
            uint32_t dst = sb + SM_A(st) + SWZ128((uint32_t)(row * 128 + seg * 16));
            const char* src = (const char*)(g_wh + (size_t)(m0 + row) * 2048 + kc * 64) + seg * 16;
            CP16(dst, src);
        }
        // B: feat tile (pre-swizzled -> linear copy)
        const char* fb = fb0 + (size_t)kc * 32768;
#pragma unroll
        for (int r = 0; r < 4; r++) {
            int q = tid + r * 512;
            CP16(sb + SM_B(st) + q * 16, fb + q * 16);
        }
    };
    auto mmastep = [&](int st, int ks) {
        int kb = ks * 32;
        uint32_t af[2][4], bb[4][4];
#pragma unroll
        for (int am = 0; am < 2; am++) {
            uint32_t off = SWZ128((uint32_t)((wm * 32 + am * 16 + arow) * 128 + kb + aseg * 16));
            ldsm_x4(sb + SM_A(st) + off, af[am]);
        }
#pragma unroll
        for (int bq = 0; bq < 4; bq++) {
            uint32_t off = SWZ128((uint32_t)((wn * 64 + bq * 16 + brow) * 128 + kb + bhalf * 16));
            ldsm_x4(sb + SM_B(st) + off, bb[bq]);
        }
#pragma unroll
        for (int am = 0; am < 2; am++)
#pragma unroll
            for (int bq = 0; bq < 4; bq++) {
                mma16816(acc[am][2 * bq], af[am], bb[bq][0], bb[bq][1]);
                mma16816(acc[am][2 * bq + 1], af[am], bb[bq][2], bb[bq][3]);
            }
    };

    // prologue: 2 chunks in flight
    cpin(0, 0); CP_COMMIT();
    cpin(1, 1); CP_COMMIT();

    for (int kc = 0; kc < 32; kc++) {
        int st = kc % 3;
        CP_WAIT1();                     // chunk kc landed
        __syncthreads();                // visible to all; prior chunk's LDSMs done
        if (kc + 2 < 32) cpin(kc + 2, (kc + 2) % 3);
        CP_COMMIT();                    // always commit (empty group ok) to keep count
        mmastep(st, 0);
        mmastep(st, 1);
        mmastep(st, 2);
        mmastep(st, 3);
    }

    // ---- epilogue: bias + relu; scatter real pairs to g_h, pseudo pairs to g_row ----
    int qrow = lane >> 2, qcol = (lane & 3) * 2;
#pragma unroll
    for (int am = 0; am < 2; am++) {
        int mb = wm * 32 + am * 16;
        float bias0 = b1[m0 + mb + qrow];
        float bias1 = b1[m0 + mb + qrow + 8];
#pragma unroll
        for (int bn = 0; bn < 8; bn++) {
            int n = wn * 64 + bn * 8 + qcol;
#pragma unroll
            for (int r = 0; r < 4; r++) {
                int mrow = mb + qrow + (r >> 1) * 8;
                int nn = n + (r & 1);
                float v = acc[am][bn][r] + ((r >> 1) ? bias1 : bias0);
                v = fmaxf(v, 0.f);
                int sa = nn >> 4, sj = nn & 15;
                int ri = six[sa], rj = six[16 + sj];
                int o = m0 + mrow;
                if (ri >= 0 && rj >= 0) {
                    float* hp = g_h + ((size_t)o << 16);
                    hp[ri * 256 + rj] = v;
                    hp[rj * 256 + ri] = v;
                } else {
                    int pa = i0 + sa, pb = j0 + sj;
                    if (pa == U && rj >= 0)      g_row[(size_t)o * 257 + rj] = v;
                    else if (pb == U && ri >= 0) g_row[(size_t)o * 257 + ri] = v;
                    else if (pa == U && pb == U) g_row[(size_t)o * 257 + 256] = v;
                }
            }
        }
    }
}

// ---------------- 7x7 conv: masked-row factorization + double-buffered prefetch ----------------
__global__ __launch_bounds__(256) void k_conv2(const float* __restrict__ w2) {
    int jb = blockIdx.x, ib = blockIdx.y;
    if (jb < ib) return;
    int g = blockIdx.z;
    __shared__ float sT[2][38][40];
    __shared__ float su[2][40];
    __shared__ float sKc[2][49];
    __shared__ float sS[2][7][32];
    __shared__ int sMi[38], sMj[38];
    int tid = threadIdx.x;
    int tx = tid & 31, ty = tid >> 5;
    int i0 = ib * 32, j0 = jb * 32;
    int rbase = ty * 4;
    float acc[4] = {0.f, 0.f, 0.f, 0.f};

    if (tid < 38) {
        int gi = i0 - 3 + tid;
        sMi[tid] = ((unsigned)gi < 256u) ? ((g_mask[gi] == 0.f) ? 1 : 0) : 2;
        int gj = j0 - 3 + tid;
        sMj[tid] = ((unsigned)gj < 256u) ? ((g_mask[gj] == 0.f) ? 1 : 0) : 2;
    }
    __syncthreads();

    float rT[6], rU, rK;
    auto ldg_stage = [&](int c) {
        const float* hp = g_h + ((size_t)c << 16);
        const float* rw = g_row + (size_t)c * 257;
#pragma unroll
        for (int q = 0; q < 6; q++) {
            rT[q] = 0.f;
            int t = tid + q * 256;
            if (t < 38 * 38) {
                int r = t / 38, cc = t - r * 38;
                if (sMi[r] == 0) {
                    int gi = i0 - 3 + r, gj = j0 - 3 + cc;
                    int mj = sMj[cc];
                    if (mj == 0)      rT[q] = hp[gi * 256 + gj];
                    else if (mj == 1) rT[q] = rw[gi];
                }
            }
        }
        rU = 0.f;
        if (tid < 38) {
            int mj = sMj[tid];
            if (mj == 0)      rU = rw[j0 - 3 + tid];
            else if (mj == 1) rU = rw[256];
        }
        rK = (tid < 49) ? w2[c * 49 + tid] : 0.f;
    };
    auto sts_stage = [&](int s) {
#pragma unroll
        for (int q = 0; q < 6; q++) {
            int t = tid + q * 256;
            if (t < 38 * 38) {
                int r = t / 38, cc = t - r * 38;
                sT[s][r][cc] = rT[q];
            }
        }
        if (tid < 38) su[s][tid] = rU;
        if (tid < 49) sKc[s][tid] = rK;
    };
    auto computeS = [&](int s) {
        if (tid < 224) {
            int a = tid >> 5, j = tid & 31;
            float v = 0.f;
#pragma unroll
            for (int b = 0; b < 7; b++) v += sKc[s][a * 7 + b] * su[s][j + b];
            sS[s][a][j] = v;
        }
    };

    ldg_stage(g * 64);
    sts_stage(0);
    __syncthreads();
    computeS(0);

    for (int ci = 0; ci < 64; ci++) {
        int c = g * 64 + ci;
        int s = ci & 1, ns = s ^ 1;
        bool have = (ci < 63);
        if (have) ldg_stage(c + 1);
        __syncthreads();
        if (have) sts_stage(ns);

        float wk[49];
#pragma unroll
        for (int q = 0; q < 49; q++) wk[q] = sKc[s][q];
#pragma unroll
        for (int rr = 0; rr < 10; rr++) {
            int cls = sMi[rbase + rr];
            if (cls == 0) {
                float seg[7];
#pragma unroll
                for (int b = 0; b < 7; b++) seg[b] = sT[s][rbase + rr][tx + b];
#pragma unroll
                for (int r = 0; r < 4; r++) {
                    int a = rr - r;
                    if (a >= 0 && a < 7) {
#pragma unroll
                        for (int b = 0; b < 7; b++)
                            acc[r] += wk[a * 7 + b] * seg[b];
                    }
                }
            } else if (cls == 1) {
#pragma unroll
                for (int r = 0; r < 4; r++) {
                    int a = rr - r;
                    if (a >= 0 && a < 7) acc[r] += sS[s][a][tx];
                }
            }
        }

        if (have) {
            __syncthreads();
            computeS(ns);
        }
    }

#pragma unroll
    for (int r = 0; r < 4; r++) {
        int i = i0 + rbase + r, j = j0 + tx;
        g_part[g * NPAIR + i * 256 + j] = acc[r];
    }
}

__global__ void k_red(const float* __restrict__ b2, float* __restrict__ out) {
    int idx = blockIdx.x * 256 + threadIdx.x;
    int i = idx >> 8, j = idx & 255;
    if (j < i) return;
    float s = b2[0];
#pragma unroll
    for (int g = 0; g < 16; g++) s += g_part[g * NPAIR + idx];
    float v = 1.f / (1.f + expf(-s));
    out[NEC + i * 256 + j] = v;
    out[NEC + j * 256 + i] = v;
}

extern "C" void kernel_launch(void* const* d_in, const int* in_sizes, int n_in,
                              void* d_out, int out_size) {
    const float* attn    = (const float*)d_in[0];
    const float* pooled  = (const float*)d_in[1];
    const int*   am      = (const int*)d_in[2];
    const float* lin1_w  = (const float*)d_in[3];
    const float* lin1_b  = (const float*)d_in[4];
    const float* cls_w   = (const float*)d_in[5];
    const float* cls_b   = (const float*)d_in[6];
    const float* conv1_w = (const float*)d_in[7];
    const float* conv1_b = (const float*)d_in[8];
    const float* conv2_w = (const float*)d_in[9];
    const float* conv2_b = (const float*)d_in[10];
    float* out = (float*)d_out;

    cudaFuncSetAttribute(k_hmma, cudaFuncAttributeMaxDynamicSharedMemorySize, SMEM_BYTES);

    k_mask<<<1, 256>>>(am);
    k_z<<<256, 256>>>(attn);
    k_wsplit<<<2048, 256>>>(conv1_w);
    k_feat<<<dim3(17, 17, 8), 256>>>();
    k_hmma<<<dim3(8, 17, 17), 512, SMEM_BYTES>>>(conv1_b);
    k_conv2<<<dim3(8, 8, 16), 256>>>(conv2_w);
    k_red<<<256, 256>>>(conv2_b, out);
    k_lin1<<<128, 256>>>(pooled, lin1_w, lin1_b);
    k_cls<<<250, 256>>>(cls_w, cls_b, out);
}

// round 17
// speedup vs baseline: 1.0600x; 1.0560x over previous
#include <cuda_runtime.h>
#include <cuda_fp16.h>
#include <cstdint>
#include <math.h>

#define L 256
#define C 1024
#define NEC 2000
#define NPAIR 65536

// ---------------- scratch (__device__ globals; no allocations) ----------------
__device__ float g_mask[L];
__device__ int   g_idx[257];                       // compacted unmasked indices
__device__ int   g_U;                              // count of unmasked positions
__device__ float g_z[C * L];                       // z[c][l], masked, transposed
__device__ float g_tmp[C];                         // lin1 output
__device__ float g_h[(size_t)C * NPAIR];           // h[o][i][j]  (sparse: real pairs only)
__device__ float g_row[(size_t)C * 257];           // pseudo-pair values
__device__ float g_part[16 * NPAIR];               // conv2 channel-group partials
__device__ __half g_wh[(size_t)C * 2048];          // W in fp16, chunk-interleaved
// feat tiles, fp16, pre-SW128-swizzled SMEM image: [tp = ib*17+jb][kc][32KB]
__device__ __align__(16) char g_feat[(size_t)289 << 20];

// ---------------- helpers ----------------
__device__ __forceinline__ uint32_t smem_to_u32(const void* p) {
    uint32_t a;
    asm("{ .reg .u64 t; cvta.to.shared.u64 t, %1; cvt.u32.u64 %0, t; }" : "=r"(a) : "l"(p));
    return a;
}
#define CVT_F16X2(res, a, b) \
    asm("cvt.rn.f16x2.f32 %0, %1, %2;" : "=r"(res) : "f"(b), "f"(a))
#define SWZ128(x) ((x) ^ (((x) >> 3) & 0x70))
#define CP16(dst, src) \
    asm volatile("cp.async.cg.shared.global [%0], [%1], 16;" :: "r"(dst), "l"(src) : "memory")
#define CP_COMMIT() asm volatile("cp.async.commit_group;" ::: "memory")
#define CP_WAIT1()  asm volatile("cp.async.wait_group 1;" ::: "memory")

__device__ __forceinline__ void ldsm_x4(uint32_t addr, uint32_t* r) {
    asm volatile("ldmatrix.sync.aligned.m8n8.x4.shared.b16 {%0,%1,%2,%3}, [%4];"
                 : "=r"(r[0]), "=r"(r[1]), "=r"(r[2]), "=r"(r[3]) : "r"(addr));
}
__device__ __forceinline__ void mma16816(float* c, const uint32_t* a, uint32_t b0, uint32_t b1) {
    asm volatile(
        "mma.sync.aligned.m16n8k16.row.col.f32.f16.f16.f32 "
        "{%0,%1,%2,%3}, {%4,%5,%6,%7}, {%8,%9}, {%0,%1,%2,%3};"
        : "+f"(c[0]), "+f"(c[1]), "+f"(c[2]), "+f"(c[3])
        : "r"(a[0]), "r"(a[1]), "r"(a[2]), "r"(a[3]), "r"(b0), "r"(b1));
}

// ---- packed f32x2 (Blackwell FFMA2 path) ----
__device__ __forceinline__ unsigned long long pk2(float x, float y) {
    unsigned long long r;
    asm("mov.b64 %0, {%1, %2};" : "=l"(r) : "f"(x), "f"(y));
    return r;
}
__device__ __forceinline__ unsigned long long bc2(float2 v) {
    unsigned long long r;
    asm("mov.b64 %0, {%1, %2};" : "=l"(r) : "f"(v.x), "f"(v.y));
    return r;
}
__device__ __forceinline__ void upk2(unsigned long long v, float& x, float& y) {
    asm("mov.b64 {%0, %1}, %2;" : "=f"(x), "=f"(y) : "l"(v));
}
__device__ __forceinline__ unsigned long long fma2v(unsigned long long a, unsigned long long b,
                                                    unsigned long long c) {
    unsigned long long d;
    asm("fma.rn.f32x2 %0, %1, %2, %3;" : "=l"(d) : "l"(a), "l"(b), "l"(c));
    return d;
}
__device__ __forceinline__ unsigned long long add2v(unsigned long long a, unsigned long long b) {
    unsigned long long d;
    asm("add.rn.f32x2 %0, %1, %2;" : "=l"(d) : "l"(a), "l"(b));
    return d;
}

// SMEM: 3-stage ring of (A 16KB + B 32KB)
#define SM_A(s) ((s) * 49152)
#define SM_B(s) ((s) * 49152 + 16384)
#define SM_SIX 147456
#define SMEM_BYTES (147456 + 128 + 1024)

// ---------------- prep: mask + compacted index list ----------------
__global__ void k_mask(const int* __restrict__ am) {
    __shared__ int red[256];
    __shared__ int scn[256];
    int l = threadIdx.x;
    int v = am[l];
    red[l] = v;
    __syncthreads();
    for (int off = 128; off; off >>= 1) {
        if (l < off) red[l] += red[l + off];
        __syncthreads();
    }
    int s = red[0];
    float m = (float)v;
    if (l == 0 || l == s) m = 0.f;
    g_mask[l] = m;
    int flag = (m != 0.f) ? 1 : 0;
    scn[l] = flag;
    __syncthreads();
    for (int off = 1; off < 256; off <<= 1) {
        int t = (l >= off) ? scn[l - off] : 0;
        __syncthreads();
        scn[l] += t;
        __syncthreads();
    }
    if (flag) g_idx[scn[l] - 1] = l;
    if (l == 255) g_U = scn[255];
}

__global__ void k_z(const float* __restrict__ attn) {
    int l = blockIdx.x;
    float m = g_mask[l];
    for (int c = threadIdx.x; c < C; c += blockDim.x)
        g_z[c * L + l] = attn[l * C + c] * m;
}

// ---------------- W -> fp16, chunk-interleaved ----------------
__global__ void k_wsplit(const float* __restrict__ W) {
    int idx = (blockIdx.x * 256 + threadIdx.x) * 4;
    int o = idx >> 11;
    int k = idx & 2047;
    int kc = k >> 6, kk = k & 63;
    int c = (kk < 32) ? (kc * 32 + kk) : (1024 + kc * 32 + kk - 32);
    float4 v = *(const float4*)(W + (size_t)o * 2048 + c);
    __half2* dh = (__half2*)(g_wh + idx);
    dh[0] = __floats2half2_rn(v.x, v.y);
    dh[1] = __floats2half2_rn(v.z, v.w);
}

// ---------------- feat generation: once per tile-pair, pre-swizzled fp16 ----------------
__global__ __launch_bounds__(256) void k_feat() {
    int ib = blockIdx.x, jb = blockIdx.y;
    int U = g_U;
    int T = (U + 16) >> 4;
    if (jb < ib || ib >= T || jb >= T) return;
    int i0 = ib * 16, j0 = jb * 16;
    int tp = ib * 17 + jb;

    __shared__ float zc[32 * 33];
    __shared__ int six[32];
    int tid = threadIdx.x;
    if (tid < 32) {
        int a = (tid < 16) ? (i0 + tid) : (j0 + tid - 16);
        six[tid] = (a < U) ? g_idx[a] : -1;
    }
    __syncthreads();

    int ii = tid >> 4, jj = tid & 15;
    char* fb0 = g_feat + ((size_t)tp << 20);

    for (int kc = blockIdx.z * 4; kc < blockIdx.z * 4 + 4; kc++) {
        __syncthreads();
        int c0 = kc * 32;
#pragma unroll
        for (int r = 0; r < 4; r++) {
            int id2 = tid + r * 256;
            int ch = id2 >> 5, l2 = id2 & 31;
            int pos = six[l2];
            zc[ch * 33 + l2] = (pos >= 0) ? g_z[(c0 + ch) * L + pos] : 0.f;
        }
        __syncthreads();
        const float* zi = zc + ii;
        const float* zj = zc + 16 + jj;
        char* fb = fb0 + (size_t)kc * 32768;
#pragma unroll
        for (int g = 0; g < 4; g++) {
            uint32_t dh[4], mh[4];
#pragma unroll
            for (int u = 0; u < 4; u++) {
                int ch = g * 8 + u * 2;
                float a0 = zi[ch * 33], a1 = zi[(ch + 1) * 33];
                float b0 = zj[ch * 33], b1v = zj[(ch + 1) * 33];
                float d0 = fabsf(a0 - b0), d1 = fabsf(a1 - b1v);
                float p0 = a0 * b0, p1 = a1 * b1v;
                uint32_t rh; CVT_F16X2(rh, d0, d1);
                uint32_t qh; CVT_F16X2(qh, p0, p1);
                dh[u] = rh; mh[u] = qh;
            }
            *(uint4*)(fb + SWZ128((uint32_t)(tid * 128 + g * 16))) =
                make_uint4(dh[0], dh[1], dh[2], dh[3]);
            *(uint4*)(fb + SWZ128((uint32_t)(tid * 128 + 64 + g * 16))) =
                make_uint4(mh[0], mh[1], mh[2], mh[3]);
        }
    }
}

// ---------------- logits head ----------------
__global__ void k_lin1(const float* __restrict__ pooled, const float* __restrict__ w,
                       const float* __restrict__ b) {
    int gw = (blockIdx.x * blockDim.x + threadIdx.x) >> 5;
    int lane = threadIdx.x & 31;
    if (gw >= C) return;
    const float* row = w + (size_t)gw * C;
    float s = 0.f;
    for (int c2 = lane; c2 < C; c2 += 32) s += row[c2] * pooled[c2];
#pragma unroll
    for (int off = 16; off; off >>= 1) s += __shfl_xor_sync(0xffffffffu, s, off);
    if (lane == 0) g_tmp[gw] = s + b[gw];
}

__global__ void k_cls(const float* __restrict__ w, const float* __restrict__ b,
                      float* __restrict__ out) {
    int gw = (blockIdx.x * blockDim.x + threadIdx.x) >> 5;
    int lane = threadIdx.x & 31;
    if (gw >= NEC) return;
    const float* row = w + (size_t)gw * C;
    float s = 0.f;
    for (int c2 = lane; c2 < C; c2 += 32) s += row[c2] * g_tmp[c2];
#pragma unroll
    for (int off = 16; off; off >>= 1) s += __shfl_xor_sync(0xffffffffu, s, off);
    if (lane == 0) out[gw] = s + b[gw];
}

// ---------------- main GEMM: pure cp.async-staged FP16 HMMA ----------------
__global__ void __launch_bounds__(512, 1) k_hmma(const float* __restrict__ b1) {
    int ib = blockIdx.y, jb = blockIdx.z;
    int U = g_U;
    int T = (U + 16) >> 4;
    if (jb < ib || ib >= T || jb >= T) return;
    int m0 = blockIdx.x * 128;
    int i0 = ib * 16, j0 = jb * 16;
    int tp = ib * 17 + jb;

    extern __shared__ char smem_raw[];
    char* sm = (char*)(((uintptr_t)smem_raw + 1023) & ~(uintptr_t)1023);
    uint32_t sb = smem_to_u32(sm);
    int* six = (int*)(sm + SM_SIX);

    int tid = threadIdx.x, wid = tid >> 5, lane = tid & 31;
    int wm = wid >> 2, wn = wid & 3;
    int arow = lane & 15, aseg = lane >> 4;
    int brow = (lane & 7) + ((lane >> 4) << 3);
    int bhalf = (lane >> 3) & 1;

    if (tid < 32) {
        int a = (tid < 16) ? (i0 + tid) : (j0 + tid - 16);
        six[tid] = (a < U) ? g_idx[a] : -1;
    }

    float acc[2][8][4];
#pragma unroll
    for (int a = 0; a < 2; a++)
#pragma unroll
        for (int b = 0; b < 8; b++)
#pragma unroll
            for (int r = 0; r < 4; r++) acc[a][b][r] = 0.f;

    const char* fb0 = g_feat + ((size_t)tp << 20);

    auto cpin = [&](int kc, int st) {
#pragma unroll
        for (int r = 0; r < 2; r++) {
            int q = tid + r * 512;
            int row = q >> 3, seg = q & 7;
            uint32_t dst = sb + SM_A(st) + SWZ128((uint32_t)(row * 128 + seg * 16));
            const char* src = (const char*)(g_wh + (size_t)(m0 + row) * 2048 + kc * 64) + seg * 16;
            CP16(dst, src);
        }
        const char* fb = fb0 + (size_t)kc * 32768;
#pragma unroll
        for (int r = 0; r < 4; r++) {
            int q = tid + r * 512;
            CP16(sb + SM_B(st) + q * 16, fb + q * 16);
        }
    };
    auto mmastep = [&](int st, int ks) {
        int kb = ks * 32;
        uint32_t af[2][4], bb[4][4];
#pragma unroll
        for (int am = 0; am < 2; am++) {
            uint32_t off = SWZ128((uint32_t)((wm * 32 + am * 16 + arow) * 128 + kb + aseg * 16));
            ldsm_x4(sb + SM_A(st) + off, af[am]);
        }
#pragma unroll
        for (int bq = 0; bq < 4; bq++) {
            uint32_t off = SWZ128((uint32_t)((wn * 64 + bq * 16 + brow) * 128 + kb + bhalf * 16));
            ldsm_x4(sb + SM_B(st) + off, bb[bq]);
        }
#pragma unroll
        for (int am = 0; am < 2; am++)
#pragma unroll
            for (int bq = 0; bq < 4; bq++) {
                mma16816(acc[am][2 * bq], af[am], bb[bq][0], bb[bq][1]);
                mma16816(acc[am][2 * bq + 1], af[am], bb[bq][2], bb[bq][3]);
            }
    };

    cpin(0, 0); CP_COMMIT();
    cpin(1, 1); CP_COMMIT();

    for (int kc = 0; kc < 32; kc++) {
        int st = kc % 3;
        CP_WAIT1();
        __syncthreads();
        if (kc + 2 < 32) cpin(kc + 2, (kc + 2) % 3);
        CP_COMMIT();
        mmastep(st, 0);
        mmastep(st, 1);
        mmastep(st, 2);
        mmastep(st, 3);
    }

    int qrow = lane >> 2, qcol = (lane & 3) * 2;
#pragma unroll
    for (int am = 0; am < 2; am++) {
        int mb = wm * 32 + am * 16;
        float bias0 = b1[m0 + mb + qrow];
        float bias1 = b1[m0 + mb + qrow + 8];
#pragma unroll
        for (int bn = 0; bn < 8; bn++) {
            int n = wn * 64 + bn * 8 + qcol;
#pragma unroll
            for (int r = 0; r < 4; r++) {
                int mrow = mb + qrow + (r >> 1) * 8;
                int nn = n + (r & 1);
                float v = acc[am][bn][r] + ((r >> 1) ? bias1 : bias0);
                v = fmaxf(v, 0.f);
                int sa = nn >> 4, sj = nn & 15;
                int ri = six[sa], rj = six[16 + sj];
                int o = m0 + mrow;
                if (ri >= 0 && rj >= 0) {
                    float* hp = g_h + ((size_t)o << 16);
                    hp[ri * 256 + rj] = v;
                    hp[rj * 256 + ri] = v;
                } else {
                    int pa = i0 + sa, pb = j0 + sj;
                    if (pa == U && rj >= 0)      g_row[(size_t)o * 257 + rj] = v;
                    else if (pb == U && ri >= 0) g_row[(size_t)o * 257 + ri] = v;
                    else if (pa == U && pb == U) g_row[(size_t)o * 257 + 256] = v;
                }
            }
        }
    }
}

// ---------------- 7x7 conv: FFMA2 (f32x2) path, 2 rows x 2 cols per thread ----------------
__global__ __launch_bounds__(256) void k_conv2(const float* __restrict__ w2) {
    int jb = blockIdx.x, ib = blockIdx.y;
    if (jb < ib) return;
    int g = blockIdx.z;
    __shared__ float sT[2][38][40];
    __shared__ float su[2][40];
    __shared__ float sKc[2][49];
    __shared__ __align__(8) unsigned long long sK2[2][49];  // packed (k,k)
    __shared__ __align__(8) float sS[2][7][32];
    __shared__ int sMi[38], sMj[38];
    int tid = threadIdx.x;
    int txp = tid & 15, typ = tid >> 4;       // cols 2txp,2txp+1; rows 2typ,2typ+1
    int i0 = ib * 32, j0 = jb * 32;

    if (tid < 38) {
        int gi = i0 - 3 + tid;
        sMi[tid] = ((unsigned)gi < 256u) ? ((g_mask[gi] == 0.f) ? 1 : 0) : 2;
        int gj = j0 - 3 + tid;
        sMj[tid] = ((unsigned)gj < 256u) ? ((g_mask[gj] == 0.f) ? 1 : 0) : 2;
    }
    __syncthreads();

    float rT[6], rU, rK;
    auto ldg_stage = [&](int c) {
        const float* hp = g_h + ((size_t)c << 16);
        const float* rw = g_row + (size_t)c * 257;
#pragma unroll
        for (int q = 0; q < 6; q++) {
            rT[q] = 0.f;
            int t = tid + q * 256;
            if (t < 38 * 38) {
                int r = t / 38, cc = t - r * 38;
                if (sMi[r] == 0) {
                    int gi = i0 - 3 + r, gj = j0 - 3 + cc;
                    int mj = sMj[cc];
                    if (mj == 0)      rT[q] = hp[gi * 256 + gj];
                    else if (mj == 1) rT[q] = rw[gi];
                }
            }
        }
        rU = 0.f;
        if (tid < 38) {
            int mj = sMj[tid];
            if (mj == 0)      rU = rw[j0 - 3 + tid];
            else if (mj == 1) rU = rw[256];
        }
        rK = (tid < 49) ? w2[c * 49 + tid] : 0.f;
    };
    auto sts_stage = [&](int s) {
#pragma unroll
        for (int q = 0; q < 6; q++) {
            int t = tid + q * 256;
            if (t < 38 * 38) {
                int r = t / 38, cc = t - r * 38;
                sT[s][r][cc] = rT[q];
            }
        }
        if (tid < 38) su[s][tid] = rU;
        if (tid < 49) {
            sKc[s][tid] = rK;
            sK2[s][tid] = pk2(rK, rK);
        }
    };
    auto computeS = [&](int s) {
        if (tid < 224) {
            int a = tid >> 5, j = tid & 31;
            float v = 0.f;
#pragma unroll
            for (int b = 0; b < 7; b++) v += sKc[s][a * 7 + b] * su[s][j + b];
            sS[s][a][j] = v;
        }
    };

    ldg_stage(g * 64);
    sts_stage(0);
    __syncthreads();
    computeS(0);

    unsigned long long a0 = 0ull, a1 = 0ull;   // packed (+0, +0)

    for (int ci = 0; ci < 64; ci++) {
        int c = g * 64 + ci;
        int s = ci & 1, ns = s ^ 1;
        bool have = (ci < 63);
        if (have) ldg_stage(c + 1);
        __syncthreads();
        if (have) sts_stage(ns);

        const unsigned long long* k2 = sK2[s];
        int rb = typ * 2;
#pragma unroll
        for (int rr = 0; rr < 8; rr++) {
            int R = rb + rr;
            int cls = sMi[R];
            if (cls == 0) {
                float2 f0 = *(const float2*)&sT[s][R][2 * txp];
                float2 f1 = *(const float2*)&sT[s][R][2 * txp + 2];
                float2 f2 = *(const float2*)&sT[s][R][2 * txp + 4];
                float2 f3 = *(const float2*)&sT[s][R][2 * txp + 6];
                unsigned long long p[7];
                p[0] = bc2(f0); p[2] = bc2(f1); p[4] = bc2(f2); p[6] = bc2(f3);
                p[1] = pk2(f0.y, f1.x);
                p[3] = pk2(f1.y, f2.x);
                p[5] = pk2(f2.y, f3.x);
                if (rr <= 6) {
#pragma unroll
                    for (int b = 0; b < 7; b++) a0 = fma2v(k2[rr * 7 + b], p[b], a0);
                }
                if (rr >= 1) {
#pragma unroll
                    for (int b = 0; b < 7; b++) a1 = fma2v(k2[(rr - 1) * 7 + b], p[b], a1);
                }
            } else if (cls == 1) {
                if (rr <= 6) a0 = add2v(a0, *(const unsigned long long*)&sS[s][rr][2 * txp]);
                if (rr >= 1) a1 = add2v(a1, *(const unsigned long long*)&sS[s][rr - 1][2 * txp]);
            }
        }

        if (have) {
            __syncthreads();
            computeS(ns);
        }
    }

    float x0, x1, y0, y1;
    upk2(a0, x0, x1);
    upk2(a1, y0, y1);
    int i = i0 + 2 * typ, j = j0 + 2 * txp;
    *(float2*)&g_part[g * NPAIR + i * 256 + j] = make_float2(x0, x1);
    *(float2*)&g_part[g * NPAIR + (i + 1) * 256 + j] = make_float2(y0, y1);
}

__global__ void k_red(const float* __restrict__ b2, float* __restrict__ out) {
    int idx = blockIdx.x * 256 + threadIdx.x;
    int i = idx >> 8, j = idx & 255;
    if (j < i) return;
    float s = b2[0];
#pragma unroll
    for (int g = 0; g < 16; g++) s += g_part[g * NPAIR + idx];
    float v = 1.f / (1.f + expf(-s));
    out[NEC + i * 256 + j] = v;
    out[NEC + j * 256 + i] = v;
}

extern "C" void kernel_launch(void* const* d_in, const int* in_sizes, int n_in,
                              void* d_out, int out_size) {
    const float* attn    = (const float*)d_in[0];
    const float* pooled  = (const float*)d_in[1];
    const int*   am      = (const int*)d_in[2];
    const float* lin1_w  = (const float*)d_in[3];
    const float* lin1_b  = (const float*)d_in[4];
    const float* cls_w   = (const float*)d_in[5];
    const float* cls_b   = (const float*)d_in[6];
    const float* conv1_w = (const float*)d_in[7];
    const float* conv1_b = (const float*)d_in[8];
    const float* conv2_w = (const float*)d_in[9];
    const float* conv2_b = (const float*)d_in[10];
    float* out = (float*)d_out;

    cudaFuncSetAttribute(k_hmma, cudaFuncAttributeMaxDynamicSharedMemorySize, SMEM_BYTES);

    k_mask<<<1, 256>>>(am);
    k_z<<<256, 256>>>(attn);
    k_wsplit<<<2048, 256>>>(conv1_w);
    k_feat<<<dim3(17, 17, 8), 256>>>();
    k_hmma<<<dim3(8, 17, 17), 512, SMEM_BYTES>>>(conv1_b);
    k_conv2<<<dim3(8, 8, 16), 256>>>(conv2_w);
    k_red<<<256, 256>>>(conv2_b, out);
    k_lin1<<<128, 256>>>(pooled, lin1_w, lin1_b);
    k_cls<<<250, 256>>>(cls_w, cls_b, out);
}